// round 1
// baseline (speedup 1.0000x reference)
#include <cuda_runtime.h>
#include <cuda_bf16.h>
#include <math.h>

#define NN 100000
#define EE 1600000
#define IN_DIM 256
#define HID 128
#define OUT_DIM 64
#define BN_EPS 1e-5f

#define SCAN_B 1024
#define NBLK ((NN + SCAN_B - 1) / SCAN_B)   // 98

// ----- static scratch (allocation-free rule) -----
__device__ int   g_cnt[NN];          // in-degree (w/o self loop)
__device__ float g_dinv[NN];
__device__ int   g_off[NN];
__device__ int   g_cur[NN];
__device__ int   g_bsum[NBLK];
__device__ int   g_csr_src[EE];
__device__ float g_csr_norm[EE];
__device__ float g_bufA[(size_t)NN * HID];
__device__ float g_bufB[(size_t)NN * HID];
__device__ float g_stats[2 * HID];   // column sums / sumsq

// ---------------------------------------------------------------------------
// Graph preprocessing
// ---------------------------------------------------------------------------
__global__ void k_zero_init() {
    int i = blockIdx.x * blockDim.x + threadIdx.x;
    if (i < NN) g_cnt[i] = 0;
    if (blockIdx.x == 0 && threadIdx.x < 2 * HID) g_stats[threadIdx.x] = 0.f;
}

__global__ void k_zero_stats() {
    if (threadIdx.x < 2 * HID) g_stats[threadIdx.x] = 0.f;
}

__global__ void k_count(const int* __restrict__ ei) {
    int e = blockIdx.x * blockDim.x + threadIdx.x;
    if (e < EE) atomicAdd(&g_cnt[ei[EE + e]], 1);
}

__global__ void k_dinv() {
    int i = blockIdx.x * blockDim.x + threadIdx.x;
    if (i < NN) g_dinv[i] = rsqrtf((float)(g_cnt[i] + 1));   // +1 self loop
}

__global__ void k_scan_local() {
    __shared__ int sm[SCAN_B];
    int t = threadIdx.x;
    int idx = blockIdx.x * SCAN_B + t;
    int v = (idx < NN) ? g_cnt[idx] : 0;
    sm[t] = v;
    __syncthreads();
    for (int ofs = 1; ofs < SCAN_B; ofs <<= 1) {
        int add = (t >= ofs) ? sm[t - ofs] : 0;
        __syncthreads();
        sm[t] += add;
        __syncthreads();
    }
    if (idx < NN) g_off[idx] = sm[t] - v;          // exclusive
    if (t == SCAN_B - 1) g_bsum[blockIdx.x] = sm[t];
}

__global__ void k_scan_blocks() {
    if (threadIdx.x == 0) {
        int run = 0;
        for (int b = 0; b < NBLK; b++) {
            int s = g_bsum[b];
            g_bsum[b] = run;
            run += s;
        }
    }
}

__global__ void k_scan_add() {
    int i = blockIdx.x * blockDim.x + threadIdx.x;
    if (i < NN) {
        int o = g_off[i] + g_bsum[i >> 10];
        g_off[i] = o;
        g_cur[i] = o;
    }
}

__global__ void k_fill(const int* __restrict__ ei) {
    int e = blockIdx.x * blockDim.x + threadIdx.x;
    if (e < EE) {
        int s = ei[e];
        int d = ei[EE + e];
        int pos = atomicAdd(&g_cur[d], 1);
        g_csr_src[pos] = s;
        g_csr_norm[pos] = g_dinv[s] * g_dinv[d];
    }
}

// ---------------------------------------------------------------------------
// fp32 GEMM  C[n x 128] = X[n x M] @ W[M x 128]
// 128x128 block tile, 256 threads, 8x8 per thread, BK=16
// ---------------------------------------------------------------------------
template<int M>
__global__ __launch_bounds__(256) void k_gemm128(const float* __restrict__ X,
                                                 const float* __restrict__ W,
                                                 float* __restrict__ C) {
    __shared__ float Xs[16][128];
    __shared__ float Ws[16][128];
    int tid = threadIdx.x;
    int row0 = blockIdx.x * 128;
    int ty = tid >> 4, tx = tid & 15;
    float acc[8][8];
#pragma unroll
    for (int i = 0; i < 8; i++)
#pragma unroll
        for (int j = 0; j < 8; j++) acc[i][j] = 0.f;

    for (int k0 = 0; k0 < M; k0 += 16) {
#pragma unroll
        for (int l = 0; l < 2; l++) {
            int t = tid + l * 256;
            int r  = t >> 2;
            int kq = (t & 3) * 4;
            int grow = row0 + r;
            float4 v = (grow < NN)
                ? *(const float4*)(X + (size_t)grow * M + k0 + kq)
                : make_float4(0.f, 0.f, 0.f, 0.f);
            Xs[kq + 0][r] = v.x; Xs[kq + 1][r] = v.y;
            Xs[kq + 2][r] = v.z; Xs[kq + 3][r] = v.w;
        }
#pragma unroll
        for (int l = 0; l < 2; l++) {
            int t = tid + l * 256;
            int kr = t >> 5;
            int cq = (t & 31) * 4;
            *(float4*)(&Ws[kr][cq]) = *(const float4*)(W + (size_t)(k0 + kr) * 128 + cq);
        }
        __syncthreads();
#pragma unroll
        for (int k = 0; k < 16; k++) {
            float a[8], b[8];
#pragma unroll
            for (int i = 0; i < 8; i++) a[i] = Xs[k][ty * 8 + i];
#pragma unroll
            for (int j = 0; j < 8; j++) b[j] = Ws[k][tx * 8 + j];
#pragma unroll
            for (int i = 0; i < 8; i++)
#pragma unroll
                for (int j = 0; j < 8; j++) acc[i][j] += a[i] * b[j];
        }
        __syncthreads();
    }
#pragma unroll
    for (int i = 0; i < 8; i++) {
        int grow = row0 + ty * 8 + i;
        if (grow < NN) {
            float4 v0 = make_float4(acc[i][0], acc[i][1], acc[i][2], acc[i][3]);
            float4 v1 = make_float4(acc[i][4], acc[i][5], acc[i][6], acc[i][7]);
            *(float4*)(C + (size_t)grow * 128 + tx * 8)     = v0;
            *(float4*)(C + (size_t)grow * 128 + tx * 8 + 4) = v1;
        }
    }
}

// ---------------------------------------------------------------------------
// Aggregation: out[i] = sum_{e in CSR[i]} norm_e * h[src_e] + dinv[i]^2 * h[i] (+bias)
// warp per node, 128 cols = 1 float4 per lane
// ---------------------------------------------------------------------------
__global__ __launch_bounds__(256) void k_agg(const float* __restrict__ h,
                                             float* __restrict__ out,
                                             const float* __restrict__ bias) {
    int warp = (blockIdx.x * blockDim.x + threadIdx.x) >> 5;
    int lane = threadIdx.x & 31;
    if (warp >= NN) return;
    int i = warp;
    float di = g_dinv[i];
    float w0 = di * di;
    float4 v = ((const float4*)(h + (size_t)i * 128))[lane];
    float4 acc = make_float4(v.x * w0, v.y * w0, v.z * w0, v.w * w0);

    int beg = g_off[i];
    int end = beg + g_cnt[i];
    int e = beg;
    // unroll by 2 for MLP
    for (; e + 1 < end; e += 2) {
        int   s0 = g_csr_src[e];
        float n0 = g_csr_norm[e];
        int   s1 = g_csr_src[e + 1];
        float n1 = g_csr_norm[e + 1];
        float4 u0 = ((const float4*)(h + (size_t)s0 * 128))[lane];
        float4 u1 = ((const float4*)(h + (size_t)s1 * 128))[lane];
        acc.x += n0 * u0.x + n1 * u1.x;
        acc.y += n0 * u0.y + n1 * u1.y;
        acc.z += n0 * u0.z + n1 * u1.z;
        acc.w += n0 * u0.w + n1 * u1.w;
    }
    if (e < end) {
        int   s0 = g_csr_src[e];
        float n0 = g_csr_norm[e];
        float4 u0 = ((const float4*)(h + (size_t)s0 * 128))[lane];
        acc.x += n0 * u0.x; acc.y += n0 * u0.y;
        acc.z += n0 * u0.z; acc.w += n0 * u0.w;
    }
    if (bias) {
        float4 b = ((const float4*)bias)[lane];
        acc.x += b.x; acc.y += b.y; acc.z += b.z; acc.w += b.w;
    }
    ((float4*)(out + (size_t)i * 128))[lane] = acc;
}

// ---------------------------------------------------------------------------
// BatchNorm
// ---------------------------------------------------------------------------
__global__ void k_bn_stats(const float* __restrict__ x) {
    int c = threadIdx.x;                 // 128 threads
    float s = 0.f, q = 0.f;
    for (int r = blockIdx.x; r < NN; r += gridDim.x) {
        float v = x[(size_t)r * 128 + c];
        s += v;
        q += v * v;
    }
    atomicAdd(&g_stats[c], s);
    atomicAdd(&g_stats[128 + c], q);
}

__global__ void k_bn_apply(float* __restrict__ x,
                           const float* __restrict__ gam,
                           const float* __restrict__ bet) {
    const float invn = 1.0f / (float)NN;
    for (size_t i = (size_t)blockIdx.x * blockDim.x + threadIdx.x;
         i < (size_t)NN * 128; i += (size_t)gridDim.x * blockDim.x) {
        int c = (int)(i & 127);
        float m  = g_stats[c] * invn;
        float vv = g_stats[128 + c] * invn - m * m;
        float sc = gam[c] * rsqrtf(vv + BN_EPS);
        float sh = bet[c] - m * sc;
        float y = x[i] * sc + sh;
        x[i] = y > 0.f ? y : 0.f;
    }
}

// ---------------------------------------------------------------------------
// Final GEMM: [mu | logstd] = p[n x 128] @ [Wmu | Wls] + [bmu | bls]
// writes mu to out[0 .. N*64), logstd to out[N*64 ..)
// ---------------------------------------------------------------------------
__global__ __launch_bounds__(256) void k_gemm_final(const float* __restrict__ P,
                                                    const float* __restrict__ Wmu,
                                                    const float* __restrict__ Wls,
                                                    const float* __restrict__ bmu,
                                                    const float* __restrict__ bls,
                                                    float* __restrict__ out) {
    __shared__ float Xs[16][128];
    __shared__ float Ws[16][128];
    int tid = threadIdx.x;
    int row0 = blockIdx.x * 128;
    int ty = tid >> 4, tx = tid & 15;
    float acc[8][8];
#pragma unroll
    for (int i = 0; i < 8; i++)
#pragma unroll
        for (int j = 0; j < 8; j++) acc[i][j] = 0.f;

    for (int k0 = 0; k0 < 128; k0 += 16) {
#pragma unroll
        for (int l = 0; l < 2; l++) {
            int t = tid + l * 256;
            int r  = t >> 2;
            int kq = (t & 3) * 4;
            int grow = row0 + r;
            float4 v = (grow < NN)
                ? *(const float4*)(P + (size_t)grow * 128 + k0 + kq)
                : make_float4(0.f, 0.f, 0.f, 0.f);
            Xs[kq + 0][r] = v.x; Xs[kq + 1][r] = v.y;
            Xs[kq + 2][r] = v.z; Xs[kq + 3][r] = v.w;
        }
#pragma unroll
        for (int l = 0; l < 2; l++) {
            int t = tid + l * 256;
            int kr = t >> 5;
            int cq = (t & 31) * 4;
            const float* srcw = (cq < 64) ? (Wmu + (size_t)(k0 + kr) * 64 + cq)
                                          : (Wls + (size_t)(k0 + kr) * 64 + (cq - 64));
            *(float4*)(&Ws[kr][cq]) = *(const float4*)srcw;
        }
        __syncthreads();
#pragma unroll
        for (int k = 0; k < 16; k++) {
            float a[8], b[8];
#pragma unroll
            for (int i = 0; i < 8; i++) a[i] = Xs[k][ty * 8 + i];
#pragma unroll
            for (int j = 0; j < 8; j++) b[j] = Ws[k][tx * 8 + j];
#pragma unroll
            for (int i = 0; i < 8; i++)
#pragma unroll
                for (int j = 0; j < 8; j++) acc[i][j] += a[i] * b[j];
        }
        __syncthreads();
    }

    bool is_mu = (tx < 8);
    int colbase = is_mu ? tx * 8 : tx * 8 - 64;           // 0..56 within its half
    const float* bias = is_mu ? bmu : bls;
    size_t half_off = is_mu ? 0 : (size_t)NN * 64;
#pragma unroll
    for (int i = 0; i < 8; i++) {
        int grow = row0 + ty * 8 + i;
        if (grow < NN) {
#pragma unroll
            for (int j = 0; j < 8; j++) {
                out[half_off + (size_t)grow * 64 + colbase + j] = acc[i][j] + bias[colbase + j];
            }
        }
    }
}

// ---------------------------------------------------------------------------
extern "C" void kernel_launch(void* const* d_in, const int* in_sizes, int n_in,
                              void* d_out, int out_size) {
    const float* x   = (const float*)d_in[0];
    const float* W1  = (const float*)d_in[1];
    const float* b1  = (const float*)d_in[2];
    const float* g1  = (const float*)d_in[3];
    const float* bt1 = (const float*)d_in[4];
    const float* W2  = (const float*)d_in[5];
    const float* b2  = (const float*)d_in[6];
    const float* g2  = (const float*)d_in[7];
    const float* bt2 = (const float*)d_in[8];
    const float* Wmu = (const float*)d_in[9];
    const float* bmu = (const float*)d_in[10];
    const float* Wls = (const float*)d_in[11];
    const float* bls = (const float*)d_in[12];
    const int*   ei  = (const int*)d_in[13];
    float* out = (float*)d_out;

    float* bufA;  cudaGetSymbolAddress((void**)&bufA, g_bufA);
    float* bufB;  cudaGetSymbolAddress((void**)&bufB, g_bufB);

    const int T = 256;
    int gN  = (NN + T - 1) / T;
    int gE  = (EE + T - 1) / T;
    int gMM = (NN + 127) / 128;          // 782 gemm blocks
    int gAgg = (NN * 32 + T - 1) / T;    // warp per node

    // --- graph preprocessing: CSR + norms ---
    k_zero_init<<<gN, T>>>();
    k_count<<<gE, T>>>(ei);
    k_dinv<<<gN, T>>>();
    k_scan_local<<<NBLK, SCAN_B>>>();
    k_scan_blocks<<<1, 32>>>();
    k_scan_add<<<gN, T>>>();
    k_fill<<<gE, T>>>(ei);

    // --- layer 1: conv -> BN -> relu ---
    k_gemm128<IN_DIM><<<gMM, T>>>(x, W1, bufA);
    k_agg<<<gAgg, T>>>(bufA, bufB, b1);
    k_bn_stats<<<512, 128>>>(bufB);
    k_bn_apply<<<4096, T>>>(bufB, g1, bt1);

    // --- layer 2: conv -> BN -> relu ---
    k_zero_stats<<<1, 256>>>();
    k_gemm128<HID><<<gMM, T>>>(bufB, W2, bufA);
    k_agg<<<gAgg, T>>>(bufA, bufB, b2);
    k_bn_stats<<<512, 128>>>(bufB);
    k_bn_apply<<<4096, T>>>(bufB, g2, bt2);

    // --- heads: p = A h2, then [mu|logstd] = p @ [Wmu|Wls] + bias ---
    k_agg<<<gAgg, T>>>(bufB, bufA, nullptr);
    k_gemm_final<<<gMM, T>>>(bufA, Wmu, Wls, bmu, bls, out);
}

// round 4
// speedup vs baseline: 1.2668x; 1.2668x over previous
#include <cuda_runtime.h>
#include <cuda_bf16.h>
#include <math.h>
#include <stdint.h>

#define NN 100000
#define EE 1600000
#define IN_DIM 256
#define HID 128
#define BN_EPS 1e-5f

#define SCAN_B 1024
#define NBLK ((NN + SCAN_B - 1) / SCAN_B)   // 98

// ----- static scratch (allocation-free rule) -----
__device__ int   g_cnt[NN];
__device__ float g_dinv[NN];
__device__ int   g_off[NN];
__device__ int   g_cur[NN];
__device__ int   g_bsum[NBLK];
__device__ int   g_csr_src[EE];
__device__ float g_csr_norm[EE];
__device__ float g_C[(size_t)NN * HID];     // fp32 scratch (gemm out / h2)
__device__ float g_D[(size_t)NN * HID];     // fp32 scratch (agg out)
__device__ __nv_bfloat16 g_Xhi[(size_t)NN * IN_DIM];  // reused as H1hi / Phi
__device__ __nv_bfloat16 g_Xlo[(size_t)NN * IN_DIM];  // reused as H1lo / Plo
__device__ __nv_bfloat16 g_W1hi[128 * 256], g_W1lo[128 * 256];
__device__ __nv_bfloat16 g_W2hi[128 * 128], g_W2lo[128 * 128];
__device__ __nv_bfloat16 g_WHhi[128 * 128], g_WHlo[128 * 128];
__device__ float g_stats[2 * HID];
__device__ float g_coef[2 * HID];

// ===========================================================================
// mma.sync m16n8k16 bf16 (sm_80+ PTX; works on plain sm_100 target)
// ===========================================================================
__device__ __forceinline__ void mma16816(float* c, const uint32_t* a, const uint32_t* b) {
    asm volatile(
        "mma.sync.aligned.m16n8k16.row.col.f32.bf16.bf16.f32 "
        "{%0,%1,%2,%3}, {%4,%5,%6,%7}, {%8,%9}, {%0,%1,%2,%3};"
        : "+f"(c[0]), "+f"(c[1]), "+f"(c[2]), "+f"(c[3])
        : "r"(a[0]), "r"(a[1]), "r"(a[2]), "r"(a[3]), "r"(b[0]), "r"(b[1]));
}

// ===========================================================================
// Graph preprocessing
// ===========================================================================
__global__ void k_zero_init() {
    int i = blockIdx.x * blockDim.x + threadIdx.x;
    if (i < NN) g_cnt[i] = 0;
    if (blockIdx.x == 0 && threadIdx.x < 2 * HID) g_stats[threadIdx.x] = 0.f;
}
__global__ void k_zero_stats() {
    if (threadIdx.x < 2 * HID) g_stats[threadIdx.x] = 0.f;
}
__global__ void k_count(const int* __restrict__ ei) {
    int e = blockIdx.x * blockDim.x + threadIdx.x;
    if (e < EE) atomicAdd(&g_cnt[ei[EE + e]], 1);
}
__global__ void k_dinv() {
    int i = blockIdx.x * blockDim.x + threadIdx.x;
    if (i < NN) g_dinv[i] = rsqrtf((float)(g_cnt[i] + 1));
}
__global__ void k_scan_local() {
    __shared__ int sm[SCAN_B];
    int t = threadIdx.x;
    int idx = blockIdx.x * SCAN_B + t;
    int v = (idx < NN) ? g_cnt[idx] : 0;
    sm[t] = v;
    __syncthreads();
    for (int ofs = 1; ofs < SCAN_B; ofs <<= 1) {
        int add = (t >= ofs) ? sm[t - ofs] : 0;
        __syncthreads();
        sm[t] += add;
        __syncthreads();
    }
    if (idx < NN) g_off[idx] = sm[t] - v;
    if (t == SCAN_B - 1) g_bsum[blockIdx.x] = sm[t];
}
__global__ void k_scan_blocks() {
    if (threadIdx.x == 0) {
        int run = 0;
        for (int b = 0; b < NBLK; b++) { int s = g_bsum[b]; g_bsum[b] = run; run += s; }
    }
}
__global__ void k_scan_add() {
    int i = blockIdx.x * blockDim.x + threadIdx.x;
    if (i < NN) { int o = g_off[i] + g_bsum[i >> 10]; g_off[i] = o; g_cur[i] = o; }
}
__global__ void k_fill(const int* __restrict__ ei) {
    int e = blockIdx.x * blockDim.x + threadIdx.x;
    if (e < EE) {
        int s = ei[e], d = ei[EE + e];
        int pos = atomicAdd(&g_cur[d], 1);
        g_csr_src[pos] = s;
        g_csr_norm[pos] = g_dinv[s] * g_dinv[d];
    }
}

// ===========================================================================
// bf16 hi/lo split conversions
// ===========================================================================
__global__ void k_split_x(const float* __restrict__ X, __nv_bfloat16* __restrict__ hi,
                          __nv_bfloat16* __restrict__ lo, int n4) {
    __nv_bfloat162* h2 = (__nv_bfloat162*)hi;
    __nv_bfloat162* l2 = (__nv_bfloat162*)lo;
    for (int i = blockIdx.x * blockDim.x + threadIdx.x; i < n4;
         i += gridDim.x * blockDim.x) {
        float4 v = ((const float4*)X)[i];
        __nv_bfloat162 a = __floats2bfloat162_rn(v.x, v.y);
        __nv_bfloat162 b = __floats2bfloat162_rn(v.z, v.w);
        float2 af = __bfloat1622float2(a), bf = __bfloat1622float2(b);
        __nv_bfloat162 al = __floats2bfloat162_rn(v.x - af.x, v.y - af.y);
        __nv_bfloat162 bl = __floats2bfloat162_rn(v.z - bf.x, v.w - bf.y);
        h2[2 * i] = a; h2[2 * i + 1] = b;
        l2[2 * i] = al; l2[2 * i + 1] = bl;
    }
}

// W [K, acols] (+optional Wb second half) -> [128(N), K] row-major (W^T) bf16 hi/lo
__global__ void k_prep_w(const float* __restrict__ Wa, const float* __restrict__ Wb,
                         int K, int acols,
                         __nv_bfloat16* __restrict__ hi, __nv_bfloat16* __restrict__ lo) {
    int i = blockIdx.x * blockDim.x + threadIdx.x;
    if (i >= 128 * K) return;
    int n = i / K, k = i - n * K;
    float v = (n < acols) ? Wa[k * acols + n] : Wb[k * acols + (n - acols)];
    __nv_bfloat16 h = __float2bfloat16_rn(v);
    hi[i] = h;
    lo[i] = __float2bfloat16_rn(v - __bfloat162float(h));
}

// ===========================================================================
// bf16-split GEMM via mma.sync: C[128-tile x 128] = A[., K] @ W^T
// 3 passes: Ahi*Whi + Ahi*Wlo + Alo*Whi, fp32 accum.
// 256 threads = 8 warps (2x4), warp tile 64x32, K-chunks of 32.
// Smem row stride 40 halfwords (80B) -> conflict-free fragment LDS.
// ===========================================================================
#define TILE_HW (128 * 40)        // halfwords per smem tile
#define TILE_B  (128 * 80)        // bytes per smem tile

template<int K, bool FINAL>
__global__ __launch_bounds__(256, 2) void k_gemm_mma(
    const __nv_bfloat16* __restrict__ Ahi, const __nv_bfloat16* __restrict__ Alo,
    const __nv_bfloat16* __restrict__ Whi, const __nv_bfloat16* __restrict__ Wlo,
    float* __restrict__ Cout, const float* __restrict__ bmu, const float* __restrict__ bls) {
    __shared__ __align__(16) __nv_bfloat16 sm[4 * TILE_HW];   // 40960 B
    char* smb = (char*)sm;
    const uint32_t* SAh = (const uint32_t*)(smb);
    const uint32_t* SAl = (const uint32_t*)(smb + TILE_B);
    const uint32_t* SWh = (const uint32_t*)(smb + 2 * TILE_B);
    const uint32_t* SWl = (const uint32_t*)(smb + 3 * TILE_B);

    int tid = threadIdx.x;
    int lane = tid & 31, wid = tid >> 5;
    int wm = wid & 1, wn = wid >> 1;          // 2 x 4 warp grid
    int row0 = blockIdx.x * 128;

    float acc[4][4][4];
#pragma unroll
    for (int mt = 0; mt < 4; mt++)
#pragma unroll
        for (int nt = 0; nt < 4; nt++)
#pragma unroll
            for (int q = 0; q < 4; q++) acc[mt][nt][q] = 0.f;

    const int NKC = K / 32;
#pragma unroll 1
    for (int kc = 0; kc < NKC; kc++) {
        // load 4 tiles: each thread moves 2 uint4 per tile
#pragma unroll
        for (int t = 0; t < 2; t++) {
            int u = tid + t * 256;            // 0..511
            int row = u >> 2, j = u & 3;      // j = 16B unit within 64B row chunk
            size_t goff = (size_t)(row0 + row) * K + kc * 32 + j * 8;
            uint4 va = make_uint4(0u, 0u, 0u, 0u), vl = va;
            if (row0 + row < NN) {
                va = *(const uint4*)(Ahi + goff);
                vl = *(const uint4*)(Alo + goff);
            }
            int soff = row * 80 + j * 16;
            *(uint4*)(smb + soff) = va;
            *(uint4*)(smb + TILE_B + soff) = vl;
            size_t woff = (size_t)row * K + kc * 32 + j * 8;
            *(uint4*)(smb + 2 * TILE_B + soff) = *(const uint4*)(Whi + woff);
            *(uint4*)(smb + 3 * TILE_B + soff) = *(const uint4*)(Wlo + woff);
        }
        __syncthreads();

#pragma unroll
        for (int ko = 0; ko < 2; ko++) {
            int kw = ko * 8 + (lane & 3);     // 32-bit word offset within row
#pragma unroll
            for (int pass = 0; pass < 3; pass++) {
                const uint32_t* Ab = (pass == 2) ? SAl : SAh;
                const uint32_t* Bb = (pass == 1) ? SWl : SWh;
                uint32_t a[4][4], b[4][2];
#pragma unroll
                for (int mt = 0; mt < 4; mt++) {
                    int r = wm * 64 + mt * 16 + (lane >> 2);
                    a[mt][0] = Ab[r * 20 + kw];
                    a[mt][1] = Ab[(r + 8) * 20 + kw];
                    a[mt][2] = Ab[r * 20 + kw + 4];
                    a[mt][3] = Ab[(r + 8) * 20 + kw + 4];
                }
#pragma unroll
                for (int nt = 0; nt < 4; nt++) {
                    int n = wn * 32 + nt * 8 + (lane >> 2);
                    b[nt][0] = Bb[n * 20 + kw];
                    b[nt][1] = Bb[n * 20 + kw + 4];
                }
#pragma unroll
                for (int mt = 0; mt < 4; mt++)
#pragma unroll
                    for (int nt = 0; nt < 4; nt++)
                        mma16816(acc[mt][nt], a[mt], b[nt]);
            }
        }
        __syncthreads();
    }

    // epilogue: direct fp32 stores (8B per fragment row pair)
#pragma unroll
    for (int mt = 0; mt < 4; mt++) {
        int r = row0 + wm * 64 + mt * 16 + (lane >> 2);
#pragma unroll
        for (int nt = 0; nt < 4; nt++) {
            int col = wn * 32 + nt * 8 + (lane & 3) * 2;
            if (!FINAL) {
                if (r < NN)
                    *(float2*)(Cout + (size_t)r * 128 + col) =
                        make_float2(acc[mt][nt][0], acc[mt][nt][1]);
                if (r + 8 < NN)
                    *(float2*)(Cout + (size_t)(r + 8) * 128 + col) =
                        make_float2(acc[mt][nt][2], acc[mt][nt][3]);
            } else {
                bool is_mu = (col < 64);
                int cc = is_mu ? col : col - 64;
                const float* bs = is_mu ? bmu : bls;
                size_t hoff = is_mu ? 0 : (size_t)NN * 64;
                float bx = __ldg(bs + cc), by = __ldg(bs + cc + 1);
                if (r < NN)
                    *(float2*)(Cout + hoff + (size_t)r * 64 + cc) =
                        make_float2(acc[mt][nt][0] + bx, acc[mt][nt][1] + by);
                if (r + 8 < NN)
                    *(float2*)(Cout + hoff + (size_t)(r + 8) * 64 + cc) =
                        make_float2(acc[mt][nt][2] + bx, acc[mt][nt][3] + by);
            }
        }
    }
}

// ===========================================================================
// Aggregation (warp per node); optional bf16-split epilogue
// ===========================================================================
template<bool SPLIT>
__global__ __launch_bounds__(256) void k_agg(const float* __restrict__ h,
                                             float* __restrict__ out,
                                             __nv_bfloat16* __restrict__ ohi,
                                             __nv_bfloat16* __restrict__ olo,
                                             const float* __restrict__ bias) {
    int warp = (blockIdx.x * blockDim.x + threadIdx.x) >> 5;
    int lane = threadIdx.x & 31;
    if (warp >= NN) return;
    int i = warp;
    float di = g_dinv[i];
    float w0 = di * di;
    float4 v = ((const float4*)(h + (size_t)i * 128))[lane];
    float4 acc = make_float4(v.x * w0, v.y * w0, v.z * w0, v.w * w0);

    int beg = g_off[i];
    int end = beg + g_cnt[i];
    int e = beg;
    for (; e + 1 < end; e += 2) {
        int   s0 = g_csr_src[e];
        float n0 = g_csr_norm[e];
        int   s1 = g_csr_src[e + 1];
        float n1 = g_csr_norm[e + 1];
        float4 u0 = ((const float4*)(h + (size_t)s0 * 128))[lane];
        float4 u1 = ((const float4*)(h + (size_t)s1 * 128))[lane];
        acc.x += n0 * u0.x + n1 * u1.x;
        acc.y += n0 * u0.y + n1 * u1.y;
        acc.z += n0 * u0.z + n1 * u1.z;
        acc.w += n0 * u0.w + n1 * u1.w;
    }
    if (e < end) {
        int   s0 = g_csr_src[e];
        float n0 = g_csr_norm[e];
        float4 u0 = ((const float4*)(h + (size_t)s0 * 128))[lane];
        acc.x += n0 * u0.x; acc.y += n0 * u0.y;
        acc.z += n0 * u0.z; acc.w += n0 * u0.w;
    }
    if (bias) {
        float4 b = ((const float4*)bias)[lane];
        acc.x += b.x; acc.y += b.y; acc.z += b.z; acc.w += b.w;
    }
    if (!SPLIT) {
        ((float4*)(out + (size_t)i * 128))[lane] = acc;
    } else {
        __nv_bfloat162 h0 = __floats2bfloat162_rn(acc.x, acc.y);
        __nv_bfloat162 h1 = __floats2bfloat162_rn(acc.z, acc.w);
        float2 f0 = __bfloat1622float2(h0), f1 = __bfloat1622float2(h1);
        __nv_bfloat162 l0 = __floats2bfloat162_rn(acc.x - f0.x, acc.y - f0.y);
        __nv_bfloat162 l1 = __floats2bfloat162_rn(acc.z - f1.x, acc.w - f1.y);
        __nv_bfloat162* ph = (__nv_bfloat162*)(ohi + (size_t)i * 128);
        __nv_bfloat162* pl = (__nv_bfloat162*)(olo + (size_t)i * 128);
        ph[lane * 2] = h0; ph[lane * 2 + 1] = h1;
        pl[lane * 2] = l0; pl[lane * 2 + 1] = l1;
    }
}

// ===========================================================================
// BatchNorm
// ===========================================================================
__global__ void k_bn_stats(const float* __restrict__ x) {
    int c = threadIdx.x;
    float s = 0.f, q = 0.f;
    for (int r = blockIdx.x; r < NN; r += gridDim.x) {
        float v = x[(size_t)r * 128 + c];
        s += v; q += v * v;
    }
    atomicAdd(&g_stats[c], s);
    atomicAdd(&g_stats[128 + c], q);
}

__global__ void k_bn_coef(const float* __restrict__ g, const float* __restrict__ bt) {
    int c = threadIdx.x;
    const float invn = 1.0f / (float)NN;
    float m = g_stats[c] * invn;
    float v = g_stats[128 + c] * invn - m * m;
    float sc = g[c] * rsqrtf(v + BN_EPS);
    g_coef[c] = sc;
    g_coef[128 + c] = bt[c] - m * sc;
}

template<bool SPLIT>
__global__ void k_bn_apply2(const float* __restrict__ src, float* __restrict__ dstf,
                            __nv_bfloat16* __restrict__ dh, __nv_bfloat16* __restrict__ dl) {
    const int n4 = NN * 32;
    for (int i = blockIdx.x * blockDim.x + threadIdx.x; i < n4;
         i += gridDim.x * blockDim.x) {
        float4 v = ((const float4*)src)[i];
        int c0 = (i << 2) & 127;
        float4 sc = *(const float4*)(g_coef + c0);
        float4 sh = *(const float4*)(g_coef + 128 + c0);
        float4 y;
        y.x = fmaxf(fmaf(v.x, sc.x, sh.x), 0.f);
        y.y = fmaxf(fmaf(v.y, sc.y, sh.y), 0.f);
        y.z = fmaxf(fmaf(v.z, sc.z, sh.z), 0.f);
        y.w = fmaxf(fmaf(v.w, sc.w, sh.w), 0.f);
        if (!SPLIT) {
            ((float4*)dstf)[i] = y;
        } else {
            __nv_bfloat162 a = __floats2bfloat162_rn(y.x, y.y);
            __nv_bfloat162 b = __floats2bfloat162_rn(y.z, y.w);
            float2 af = __bfloat1622float2(a), bf = __bfloat1622float2(b);
            __nv_bfloat162 al = __floats2bfloat162_rn(y.x - af.x, y.y - af.y);
            __nv_bfloat162 bl = __floats2bfloat162_rn(y.z - bf.x, y.w - bf.y);
            ((__nv_bfloat162*)dh)[2 * i] = a; ((__nv_bfloat162*)dh)[2 * i + 1] = b;
            ((__nv_bfloat162*)dl)[2 * i] = al; ((__nv_bfloat162*)dl)[2 * i + 1] = bl;
        }
    }
}

// ===========================================================================
extern "C" void kernel_launch(void* const* d_in, const int* in_sizes, int n_in,
                              void* d_out, int out_size) {
    const float* x   = (const float*)d_in[0];
    const float* W1  = (const float*)d_in[1];
    const float* b1  = (const float*)d_in[2];
    const float* g1  = (const float*)d_in[3];
    const float* bt1 = (const float*)d_in[4];
    const float* W2  = (const float*)d_in[5];
    const float* b2  = (const float*)d_in[6];
    const float* g2  = (const float*)d_in[7];
    const float* bt2 = (const float*)d_in[8];
    const float* Wmu = (const float*)d_in[9];
    const float* bmu = (const float*)d_in[10];
    const float* Wls = (const float*)d_in[11];
    const float* bls = (const float*)d_in[12];
    const int*   ei  = (const int*)d_in[13];
    float* out = (float*)d_out;

    float *C, *D;
    __nv_bfloat16 *Xhi, *Xlo, *W1h, *W1l, *W2h, *W2l, *WHh, *WHl;
    cudaGetSymbolAddress((void**)&C, g_C);
    cudaGetSymbolAddress((void**)&D, g_D);
    cudaGetSymbolAddress((void**)&Xhi, g_Xhi);
    cudaGetSymbolAddress((void**)&Xlo, g_Xlo);
    cudaGetSymbolAddress((void**)&W1h, g_W1hi);
    cudaGetSymbolAddress((void**)&W1l, g_W1lo);
    cudaGetSymbolAddress((void**)&W2h, g_W2hi);
    cudaGetSymbolAddress((void**)&W2l, g_W2lo);
    cudaGetSymbolAddress((void**)&WHh, g_WHhi);
    cudaGetSymbolAddress((void**)&WHl, g_WHlo);

    const int T = 256;
    int gN = (NN + T - 1) / T;
    int gE = (EE + T - 1) / T;
    int gMM = (NN + 127) / 128;          // 782
    int gAgg = (NN * 32 + T - 1) / T;

    // --- graph preprocessing ---
    k_zero_init<<<gN, T>>>();
    k_count<<<gE, T>>>(ei);
    k_dinv<<<gN, T>>>();
    k_scan_local<<<NBLK, SCAN_B>>>();
    k_scan_blocks<<<1, 32>>>();
    k_scan_add<<<gN, T>>>();
    k_fill<<<gE, T>>>(ei);

    // --- input / weight splits ---
    k_split_x<<<4096, T>>>(x, Xhi, Xlo, NN * IN_DIM / 4);
    k_prep_w<<<(128 * 256 + 255) / 256, 256>>>(W1, nullptr, 256, 128, W1h, W1l);
    k_prep_w<<<(128 * 128 + 255) / 256, 256>>>(W2, nullptr, 128, 128, W2h, W2l);
    k_prep_w<<<(128 * 128 + 255) / 256, 256>>>(Wmu, Wls, 128, 64, WHh, WHl);

    // --- layer 1 ---
    k_gemm_mma<IN_DIM, false><<<gMM, 256>>>(Xhi, Xlo, W1h, W1l, C, nullptr, nullptr);
    k_agg<false><<<gAgg, T>>>(C, D, nullptr, nullptr, b1);
    k_bn_stats<<<512, 128>>>(D);
    k_bn_coef<<<1, 128>>>(g1, bt1);
    k_bn_apply2<true><<<2048, T>>>(D, nullptr, Xhi, Xlo);   // H1 split (reuse X bufs)

    // --- layer 2 ---
    k_gemm_mma<HID, false><<<gMM, 256>>>(Xhi, Xlo, W2h, W2l, C, nullptr, nullptr);
    k_agg<false><<<gAgg, T>>>(C, D, nullptr, nullptr, b2);
    k_zero_stats<<<1, 256>>>();
    k_bn_stats<<<512, 128>>>(D);
    k_bn_coef<<<1, 128>>>(g2, bt2);
    k_bn_apply2<false><<<2048, T>>>(D, C, nullptr, nullptr);  // h2 fp32 -> C

    // --- heads: p = A h2 (split epilogue), then [mu|ls] = p @ WH + bias ---
    k_agg<true><<<gAgg, T>>>(C, nullptr, Xhi, Xlo, nullptr);
    k_gemm_mma<HID, true><<<gMM, 256>>>(Xhi, Xlo, WHh, WHl, out, bmu, bls);
}